// round 6
// baseline (speedup 1.0000x reference)
#include <cuda_runtime.h>
#include <cuda_bf16.h>

#define NP 512
#define NT 1024

typedef unsigned long long u64;

// ---- packed f32x2 helpers (SASS FFMA2/FADD2/FMUL2 — only reachable via PTX) ----
__device__ __forceinline__ u64 pk2(float lo, float hi) {
    u64 r; asm("mov.b64 %0,{%1,%2};" : "=l"(r) : "f"(lo), "f"(hi)); return r;
}
__device__ __forceinline__ u64 fma2(u64 a, u64 b, u64 c) {
    u64 d; asm("fma.rn.f32x2 %0,%1,%2,%3;" : "=l"(d) : "l"(a), "l"(b), "l"(c)); return d;
}
__device__ __forceinline__ u64 add2(u64 a, u64 b) {
    u64 d; asm("add.rn.f32x2 %0,%1,%2;" : "=l"(d) : "l"(a), "l"(b)); return d;
}
__device__ __forceinline__ u64 mul2(u64 a, u64 b) {
    u64 d; asm("mul.rn.f32x2 %0,%1,%2;" : "=l"(d) : "l"(a), "l"(b)); return d;
}
// sign-flip both packed lanes on the ALU pipe (2x LOP3, keeps fma pipe free)
__device__ __forceinline__ u64 neg2(u64 a) { return a ^ 0x8000000080000000ULL; }
// bit-hack reciprocal seed on both packed halves (2 IADD on the alu pipe)
__device__ __forceinline__ u64 rcpseed2(u64 s) {
    u64 d;
    asm("{ .reg .b32 lo,hi;\n\t"
        "  mov.b64 {lo,hi}, %1;\n\t"
        "  sub.u32 lo, 0x7EF311C3, lo;\n\t"
        "  sub.u32 hi, 0x7EF311C3, hi;\n\t"
        "  mov.b64 %0, {lo,hi}; }" : "=l"(d) : "l"(s));
    return d;
}

// One block per batch element; 1024 threads (32 warps -> 8/SMSP for latency).
// Lane-packing over PARTICLES: smem u64 px[p] = (x[p], x[(p+256)&511]).
// Thread t: i = t & 255, h = t >> 8 in {0..3}; owns lane pair (i, i+256) and
// quarter k-range kb = 1 + 64*h .. kb+63. One packed unit at offset k:
//   j = i + k <= 511+... (i<=255, k<=256 -> j<=511), px[j] gives BOTH
//   j-coordinates with one LDS.64 — contiguous, conflict-free.
// Coverage: k=1..255 hits every unordered pair once; k=256 (h=3 last unit)
// computes each distance-256 pair twice in its two lanes -> weight 1/2.
// Total LJ = 2 * sum.
__global__ __launch_bounds__(NT, 1)
void lj_osc_kernel(const float* __restrict__ x, float* __restrict__ out) {
    __shared__ __align__(16) u64 px[NP];
    __shared__ __align__(16) u64 py[NP];
    __shared__ __align__(16) u64 pz[NP];
    __shared__ float red[5][32];

    const int b = blockIdx.x;
    const int t = threadIdx.x;
    const int i = t & 255;
    const int h = t >> 8;
    const float* __restrict__ xb = x + (size_t)b * (NP * 3);

    // Coalesced load of 1536 floats; scatter into packed u64 SoA arrays.
    // x[p] goes to lane0 of entry p and lane1 of entry (p+256)&511.
    {
        int e, p, d;
#define SCATTER(VAL, EE) {                                              \
        e = (EE); p = e / 3; d = e - 3 * p;                             \
        u64* arr = (d == 0) ? px : (d == 1) ? py : pz;                  \
        float* f = (float*)arr;                                         \
        f[2 * p] = VAL;                                                 \
        f[2 * ((p + 256) & 511) + 1] = VAL; }
        float v0 = xb[t];
        SCATTER(v0, t)
        if (t < 512) {
            float v1 = xb[t + 1024];
            SCATTER(v1, t + 1024)
        }
#undef SCATTER
    }
    __syncthreads();

    // Thread's own packed coords (lanes i and i+256), negated once.
    const u64 qx = px[i];
    const u64 qy = py[i];
    const u64 qz = pz[i];
    const u64 nxi = neg2(qx);
    const u64 nyi = neg2(qy);
    const u64 nzi = neg2(qz);

    const u64 EPS  = pk2(1e-6f, 1e-6f);
    const u64 TWO  = pk2(2.0f, 2.0f);
    const u64 NEG2 = pk2(-2.0f, -2.0f);

    u64 a0 = 0, a1 = 0, a2 = 0, a3 = 0;

// One packed unit at offset K: one LDS.64 per coordinate.
#define UNIT(ACC, K) {                                                   \
        int j = i + (K);                                                 \
        u64 xj = px[j];                                                  \
        u64 yj = py[j];                                                  \
        u64 zj = pz[j];                                                  \
        u64 dx = add2(xj, nxi);                                          \
        u64 dy = add2(yj, nyi);                                          \
        u64 dz = add2(zj, nzi);                                          \
        u64 s  = fma2(dx, dx, fma2(dy, dy, fma2(dz, dz, EPS)));          \
        u64 yv = rcpseed2(s);                                            \
        u64 sn = neg2(s);                                                \
        yv = mul2(yv, fma2(sn, yv, TWO));                                \
        yv = mul2(yv, fma2(sn, yv, TWO));                                \
        u64 i6 = mul2(mul2(yv, yv), yv);                                 \
        ACC = fma2(i6, add2(i6, NEG2), ACC); }

    const int kb = 1 + (h << 6);   // 1, 65, 129, 193

    // Four interleaved independent chains, 16 units each; last unit of the
    // last chain handled separately (k = kb+63; for h=3 that is k=256).
    for (int m = 0; m < 15; ++m) {
        UNIT(a0, kb + m);
        UNIT(a1, kb + 16 + m);
        UNIT(a2, kb + 32 + m);
        UNIT(a3, kb + 48 + m);
    }
    UNIT(a0, kb + 15);
    UNIT(a1, kb + 31);
    UNIT(a2, kb + 47);
    // k = kb+63: for h=3 this is k=256 where both lanes duplicate each
    // distance-256 pair -> weight 1/2; otherwise weight 1.
    {
        int j = i + kb + 63;
        u64 xj = px[j];
        u64 yj = py[j];
        u64 zj = pz[j];
        u64 dx = add2(xj, nxi);
        u64 dy = add2(yj, nyi);
        u64 dz = add2(zj, nzi);
        u64 s  = fma2(dx, dx, fma2(dy, dy, fma2(dz, dz, EPS)));
        u64 yv = rcpseed2(s);
        u64 sn = neg2(s);
        yv = mul2(yv, fma2(sn, yv, TWO));
        yv = mul2(yv, fma2(sn, yv, TWO));
        u64 i6 = mul2(mul2(yv, yv), yv);
        u64 term = mul2(i6, add2(i6, NEG2));
        float w = (h == 3) ? 0.5f : 1.0f;
        a3 = fma2(term, pk2(w, w), a3);
    }
#undef UNIT

    u64 accp = add2(add2(a0, a1), add2(a2, a3));
    float al, ah;
    asm("mov.b64 {%0,%1}, %2;" : "=f"(al), "=f"(ah) : "l"(accp));
    float acc = al + ah;

    // Oscillator terms: only h=0 threads contribute (each particle once).
    float sx = 0.f, sy = 0.f, sz = 0.f, ssq = 0.f;
    if (h == 0) {
        float xlo, xhi, ylo, yhi, zlo, zhi;
        asm("mov.b64 {%0,%1}, %2;" : "=f"(xlo), "=f"(xhi) : "l"(qx));
        asm("mov.b64 {%0,%1}, %2;" : "=f"(ylo), "=f"(yhi) : "l"(qy));
        asm("mov.b64 {%0,%1}, %2;" : "=f"(zlo), "=f"(zhi) : "l"(qz));
        sx = xlo + xhi;
        sy = ylo + yhi;
        sz = zlo + zhi;
        ssq = fmaf(xlo, xlo, fmaf(ylo, ylo, zlo * zlo))
            + fmaf(xhi, xhi, fmaf(yhi, yhi, zhi * zhi));
    }

    // Block reduction of 5 values: acc(LJ), sum_x, sum_y, sum_z, sum_sq
    float v[5] = {acc, sx, sy, sz, ssq};
    const unsigned FULL = 0xFFFFFFFFu;
    #pragma unroll
    for (int q = 0; q < 5; ++q) {
        float r = v[q];
        r += __shfl_down_sync(FULL, r, 16);
        r += __shfl_down_sync(FULL, r, 8);
        r += __shfl_down_sync(FULL, r, 4);
        r += __shfl_down_sync(FULL, r, 2);
        r += __shfl_down_sync(FULL, r, 1);
        v[q] = r;
    }
    const int warp = t >> 5;
    const int lane = t & 31;
    if (lane == 0) {
        #pragma unroll
        for (int q = 0; q < 5; ++q) red[q][warp] = v[q];
    }
    __syncthreads();
    if (warp == 0) {
        float r[5];
        #pragma unroll
        for (int q = 0; q < 5; ++q) {
            float val = red[q][lane];
            val += __shfl_down_sync(FULL, val, 16);
            val += __shfl_down_sync(FULL, val, 8);
            val += __shfl_down_sync(FULL, val, 4);
            val += __shfl_down_sync(FULL, val, 2);
            val += __shfl_down_sync(FULL, val, 1);
            r[q] = val;
        }
        if (lane == 0) {
            float lj_total = 2.0f * r[0];
            float mean_sq = (r[1] * r[1] + r[2] * r[2] + r[3] * r[3]) * (1.0f / NP);
            float osc = 0.5f * (r[4] - mean_sq);
            out[b] = lj_total + osc;
        }
    }
}

extern "C" void kernel_launch(void* const* d_in, const int* in_sizes, int n_in,
                              void* d_out, int out_size) {
    const float* x = (const float*)d_in[0];
    float* out = (float*)d_out;
    int batches = in_sizes[0] / (NP * 3);   // 128
    lj_osc_kernel<<<batches, NT>>>(x, out);
}

// round 7
// speedup vs baseline: 1.0148x; 1.0148x over previous
#include <cuda_runtime.h>
#include <cuda_bf16.h>

#define NP 512

typedef unsigned long long u64;

// ---- packed f32x2 helpers (SASS FFMA2/FADD2/FMUL2 — only reachable via PTX) ----
__device__ __forceinline__ u64 pk2(float lo, float hi) {
    u64 r; asm("mov.b64 %0,{%1,%2};" : "=l"(r) : "f"(lo), "f"(hi)); return r;
}
__device__ __forceinline__ u64 fma2(u64 a, u64 b, u64 c) {
    u64 d; asm("fma.rn.f32x2 %0,%1,%2,%3;" : "=l"(d) : "l"(a), "l"(b), "l"(c)); return d;
}
__device__ __forceinline__ u64 add2(u64 a, u64 b) {
    u64 d; asm("add.rn.f32x2 %0,%1,%2;" : "=l"(d) : "l"(a), "l"(b)); return d;
}
__device__ __forceinline__ u64 mul2(u64 a, u64 b) {
    u64 d; asm("mul.rn.f32x2 %0,%1,%2;" : "=l"(d) : "l"(a), "l"(b)); return d;
}
// sign-flip both packed lanes on the ALU pipe (2x LOP3, keeps fma pipe free)
__device__ __forceinline__ u64 neg2(u64 a) { return a ^ 0x8000000080000000ULL; }
// MUFU.RCP on both packed halves: 2 ops on the MUFU pipe (rt8), which is idle.
// Replaces bit-seed + 2 Newton steps = 4 fma-pipe ops. ~1ulp accurate.
__device__ __forceinline__ u64 rcp2(u64 s) {
    float lo, hi, rl, rh;
    asm("mov.b64 {%0,%1}, %2;" : "=f"(lo), "=f"(hi) : "l"(s));
    asm("rcp.approx.f32 %0, %1;" : "=f"(rl) : "f"(lo));
    asm("rcp.approx.f32 %0, %1;" : "=f"(rh) : "f"(hi));
    u64 r; asm("mov.b64 %0,{%1,%2};" : "=l"(r) : "f"(rl), "f"(rh));
    return r;
}

// One block per batch element; 512 threads.
// Lane-packing over PARTICLES: smem holds u64 px[p] = (x[p], x[(p+256)&511]).
// Thread t: i = t & 255, h = t >> 8. It owns lane pair (i, i+256) and the
// k-range h=0 -> k=1..128, h=1 -> k=129..256. One packed unit at offset k:
//   j = i + k,  px[j] = (x[i+k], x[(i+k+256)&511])
// computes pairs (i, i+k) and (i+256, i+256+k mod 512) with ONE LDS.64 per
// coordinate — contiguous, conflict-free, no register marshalling.
// Cyclic-offset coverage: k=1..255 hits every unordered pair exactly once;
// k=256 computes each distance-256 pair twice -> weight 1/2. Total = 2*sum.
__global__ __launch_bounds__(NP, 1)
void lj_osc_kernel(const float* __restrict__ x, float* __restrict__ out) {
    __shared__ __align__(16) u64 px[NP];
    __shared__ __align__(16) u64 py[NP];
    __shared__ __align__(16) u64 pz[NP];
    __shared__ float red[5][16];

    const int b = blockIdx.x;
    const int t = threadIdx.x;
    const int i = t & 255;
    const int h = t >> 8;
    const float* __restrict__ xb = x + (size_t)b * (NP * 3);

    // Coalesced load of 1536 floats; scatter into packed u64 SoA arrays.
    // x[p] goes to lane0 of entry p and lane1 of entry (p+256)&511.
    {
        float v0 = xb[t];
        float v1 = xb[t + 512];
        float v2 = xb[t + 1024];
        int e, p, d;
#define SCATTER(VAL, EE) {                                              \
        e = (EE); p = e / 3; d = e - 3 * p;                             \
        u64* arr = (d == 0) ? px : (d == 1) ? py : pz;                  \
        float* f = (float*)arr;                                         \
        f[2 * p] = VAL;                                                 \
        f[2 * ((p + 256) & 511) + 1] = VAL; }
        SCATTER(v0, t)
        SCATTER(v1, t + 512)
        SCATTER(v2, t + 1024)
#undef SCATTER
    }
    __syncthreads();

    // Thread's own packed coords (lanes i and i+256), negated once.
    const u64 qx = px[i];
    const u64 qy = py[i];
    const u64 qz = pz[i];
    const u64 nxi = neg2(qx);
    const u64 nyi = neg2(qy);
    const u64 nzi = neg2(qz);

    const u64 EPS  = pk2(1e-6f, 1e-6f);
    const u64 NEG2 = pk2(-2.0f, -2.0f);

    u64 a0 = 0, a1 = 0, a2 = 0, a3 = 0;

// One packed unit at offset K: one LDS.64 per coordinate; 10 fma-pipe ops
// (3 diff, 3 dist2, 2 cube, 2 accumulate) + 2 MUFU.RCP on the mufu pipe.
#define UNIT(ACC, K) {                                                   \
        int j = i + (K);                                                 \
        u64 xj = px[j];                                                  \
        u64 yj = py[j];                                                  \
        u64 zj = pz[j];                                                  \
        u64 dx = add2(xj, nxi);                                          \
        u64 dy = add2(yj, nyi);                                          \
        u64 dz = add2(zj, nzi);                                          \
        u64 s  = fma2(dx, dx, fma2(dy, dy, fma2(dz, dz, EPS)));          \
        u64 yv = rcp2(s);                                                \
        u64 i6 = mul2(mul2(yv, yv), yv);                                 \
        ACC = fma2(i6, add2(i6, NEG2), ACC); }

    const int kb = 1 + (h << 7);   // 1 (h=0) or 129 (h=1)

    // Four interleaved independent chains, 31+1 units each.
    for (int m = 0; m < 31; ++m) {
        UNIT(a0, kb + m);
        UNIT(a1, kb + 32 + m);
        UNIT(a2, kb + 64 + m);
        UNIT(a3, kb + 96 + m);
    }
    UNIT(a0, kb + 31);
    UNIT(a1, kb + 63);
    UNIT(a2, kb + 95);
    // Last unit of chain 3: k = kb+127 (=128 for h=0, =256 for h=1).
    // k=256 computes each distance-256 pair twice -> weight 1/2.
    {
        int j = i + kb + 127;
        u64 xj = px[j];
        u64 yj = py[j];
        u64 zj = pz[j];
        u64 dx = add2(xj, nxi);
        u64 dy = add2(yj, nyi);
        u64 dz = add2(zj, nzi);
        u64 s  = fma2(dx, dx, fma2(dy, dy, fma2(dz, dz, EPS)));
        u64 yv = rcp2(s);
        u64 i6 = mul2(mul2(yv, yv), yv);
        u64 term = mul2(i6, add2(i6, NEG2));
        float w = h ? 0.5f : 1.0f;
        a3 = fma2(term, pk2(w, w), a3);
    }
#undef UNIT

    u64 accp = add2(add2(a0, a1), add2(a2, a3));
    float al, ah;
    asm("mov.b64 {%0,%1}, %2;" : "=f"(al), "=f"(ah) : "l"(accp));
    float acc = al + ah;

    // Oscillator terms: only h=0 threads contribute (each particle once).
    float sx = 0.f, sy = 0.f, sz = 0.f, ssq = 0.f;
    if (h == 0) {
        float xlo, xhi, ylo, yhi, zlo, zhi;
        asm("mov.b64 {%0,%1}, %2;" : "=f"(xlo), "=f"(xhi) : "l"(qx));
        asm("mov.b64 {%0,%1}, %2;" : "=f"(ylo), "=f"(yhi) : "l"(qy));
        asm("mov.b64 {%0,%1}, %2;" : "=f"(zlo), "=f"(zhi) : "l"(qz));
        sx = xlo + xhi;
        sy = ylo + yhi;
        sz = zlo + zhi;
        ssq = fmaf(xlo, xlo, fmaf(ylo, ylo, zlo * zlo))
            + fmaf(xhi, xhi, fmaf(yhi, yhi, zhi * zhi));
    }

    // Block reduction of 5 values: acc(LJ), sum_x, sum_y, sum_z, sum_sq
    float v[5] = {acc, sx, sy, sz, ssq};
    const unsigned FULL = 0xFFFFFFFFu;
    #pragma unroll
    for (int q = 0; q < 5; ++q) {
        float r = v[q];
        r += __shfl_down_sync(FULL, r, 16);
        r += __shfl_down_sync(FULL, r, 8);
        r += __shfl_down_sync(FULL, r, 4);
        r += __shfl_down_sync(FULL, r, 2);
        r += __shfl_down_sync(FULL, r, 1);
        v[q] = r;
    }
    const int warp = t >> 5;
    const int lane = t & 31;
    if (lane == 0) {
        #pragma unroll
        for (int q = 0; q < 5; ++q) red[q][warp] = v[q];
    }
    __syncthreads();
    if (warp == 0) {
        float r[5];
        #pragma unroll
        for (int q = 0; q < 5; ++q) {
            float val = (lane < 16) ? red[q][lane] : 0.0f;
            val += __shfl_down_sync(FULL, val, 8);
            val += __shfl_down_sync(FULL, val, 4);
            val += __shfl_down_sync(FULL, val, 2);
            val += __shfl_down_sync(FULL, val, 1);
            r[q] = val;
        }
        if (lane == 0) {
            float lj_total = 2.0f * r[0];
            float mean_sq = (r[1] * r[1] + r[2] * r[2] + r[3] * r[3]) * (1.0f / NP);
            float osc = 0.5f * (r[4] - mean_sq);
            out[b] = lj_total + osc;
        }
    }
}

extern "C" void kernel_launch(void* const* d_in, const int* in_sizes, int n_in,
                              void* d_out, int out_size) {
    const float* x = (const float*)d_in[0];
    float* out = (float*)d_out;
    int batches = in_sizes[0] / (NP * 3);   // 128
    lj_osc_kernel<<<batches, NP>>>(x, out);
}

// round 8
// speedup vs baseline: 1.0323x; 1.0172x over previous
#include <cuda_runtime.h>
#include <cuda_bf16.h>

#define NP 512

typedef unsigned long long u64;

// ---- packed f32x2 helpers (SASS FFMA2/FADD2/FMUL2 — only reachable via PTX) ----
__device__ __forceinline__ u64 pk2(float lo, float hi) {
    u64 r; asm("mov.b64 %0,{%1,%2};" : "=l"(r) : "f"(lo), "f"(hi)); return r;
}
__device__ __forceinline__ u64 fma2(u64 a, u64 b, u64 c) {
    u64 d; asm("fma.rn.f32x2 %0,%1,%2,%3;" : "=l"(d) : "l"(a), "l"(b), "l"(c)); return d;
}
__device__ __forceinline__ u64 add2(u64 a, u64 b) {
    u64 d; asm("add.rn.f32x2 %0,%1,%2;" : "=l"(d) : "l"(a), "l"(b)); return d;
}
__device__ __forceinline__ u64 mul2(u64 a, u64 b) {
    u64 d; asm("mul.rn.f32x2 %0,%1,%2;" : "=l"(d) : "l"(a), "l"(b)); return d;
}
// sign-flip both packed lanes on the ALU pipe (2x LOP3, keeps fma pipe free)
__device__ __forceinline__ u64 neg2(u64 a) { return a ^ 0x8000000080000000ULL; }
// MUFU.RCP on both packed halves: 2 ops on the MUFU pipe (rt8), which is idle.
// Replaces bit-seed + 2 Newton steps = 4 fma-pipe ops. ~1ulp accurate.
__device__ __forceinline__ u64 rcp2(u64 s) {
    float lo, hi, rl, rh;
    asm("mov.b64 {%0,%1}, %2;" : "=f"(lo), "=f"(hi) : "l"(s));
    asm("rcp.approx.f32 %0, %1;" : "=f"(rl) : "f"(lo));
    asm("rcp.approx.f32 %0, %1;" : "=f"(rh) : "f"(hi));
    u64 r; asm("mov.b64 %0,{%1,%2};" : "=l"(r) : "f"(rl), "f"(rh));
    return r;
}

// One block per batch element; 512 threads.
// Lane-packing over PARTICLES: smem holds u64 px[p] = (x[p], x[(p+256)&511]).
// Thread t: i = t & 255, h = t >> 8. It owns lane pair (i, i+256) and the
// k-range h=0 -> k=1..128, h=1 -> k=129..256. One packed unit at offset k:
//   j = i + k,  px[j] = (x[i+k], x[(i+k+256)&511])
// computes pairs (i, i+k) and (i+256, i+256+k mod 512) with ONE LDS.64 per
// coordinate — contiguous, conflict-free, no register marshalling.
// Cyclic-offset coverage: k=1..255 hits every unordered pair exactly once;
// k=256 computes each distance-256 pair twice -> weight 1/2. Total = 2*sum.
__global__ __launch_bounds__(NP, 1)
void lj_osc_kernel(const float* __restrict__ x, float* __restrict__ out) {
    __shared__ __align__(16) u64 px[NP];
    __shared__ __align__(16) u64 py[NP];
    __shared__ __align__(16) u64 pz[NP];
    __shared__ float red[5][16];

    const int b = blockIdx.x;
    const int t = threadIdx.x;
    const int i = t & 255;
    const int h = t >> 8;
    const float* __restrict__ xb = x + (size_t)b * (NP * 3);

    // Coalesced load of 1536 floats; scatter into packed u64 SoA arrays.
    // x[p] goes to lane0 of entry p and lane1 of entry (p+256)&511.
    {
        float v0 = xb[t];
        float v1 = xb[t + 512];
        float v2 = xb[t + 1024];
        int e, p, d;
#define SCATTER(VAL, EE) {                                              \
        e = (EE); p = e / 3; d = e - 3 * p;                             \
        u64* arr = (d == 0) ? px : (d == 1) ? py : pz;                  \
        float* f = (float*)arr;                                         \
        f[2 * p] = VAL;                                                 \
        f[2 * ((p + 256) & 511) + 1] = VAL; }
        SCATTER(v0, t)
        SCATTER(v1, t + 512)
        SCATTER(v2, t + 1024)
#undef SCATTER
    }
    __syncthreads();

    // Thread's own packed coords (lanes i and i+256), negated once.
    const u64 qx = px[i];
    const u64 qy = py[i];
    const u64 qz = pz[i];
    const u64 nxi = neg2(qx);
    const u64 nyi = neg2(qy);
    const u64 nzi = neg2(qz);

    const u64 EPS  = pk2(1e-6f, 1e-6f);
    const u64 NEG2 = pk2(-2.0f, -2.0f);

    u64 a0 = 0, a1 = 0, a2 = 0, a3 = 0;

// One packed unit at offset K: one LDS.64 per coordinate; 10 fma-pipe ops
// (3 diff, 3 dist2, 2 cube, 2 accumulate) + 2 MUFU.RCP on the mufu pipe.
#define UNIT(ACC, K) {                                                   \
        int j = i + (K);                                                 \
        u64 xj = px[j];                                                  \
        u64 yj = py[j];                                                  \
        u64 zj = pz[j];                                                  \
        u64 dx = add2(xj, nxi);                                          \
        u64 dy = add2(yj, nyi);                                          \
        u64 dz = add2(zj, nzi);                                          \
        u64 s  = fma2(dx, dx, fma2(dy, dy, fma2(dz, dz, EPS)));          \
        u64 yv = rcp2(s);                                                \
        u64 i6 = mul2(mul2(yv, yv), yv);                                 \
        ACC = fma2(i6, add2(i6, NEG2), ACC); }

    const int kb = 1 + (h << 7);   // 1 (h=0) or 129 (h=1)

    // Four interleaved independent chains, 31+1 units each.
    for (int m = 0; m < 31; ++m) {
        UNIT(a0, kb + m);
        UNIT(a1, kb + 32 + m);
        UNIT(a2, kb + 64 + m);
        UNIT(a3, kb + 96 + m);
    }
    UNIT(a0, kb + 31);
    UNIT(a1, kb + 63);
    UNIT(a2, kb + 95);
    // Last unit of chain 3: k = kb+127 (=128 for h=0, =256 for h=1).
    // k=256 computes each distance-256 pair twice -> weight 1/2.
    {
        int j = i + kb + 127;
        u64 xj = px[j];
        u64 yj = py[j];
        u64 zj = pz[j];
        u64 dx = add2(xj, nxi);
        u64 dy = add2(yj, nyi);
        u64 dz = add2(zj, nzi);
        u64 s  = fma2(dx, dx, fma2(dy, dy, fma2(dz, dz, EPS)));
        u64 yv = rcp2(s);
        u64 i6 = mul2(mul2(yv, yv), yv);
        u64 term = mul2(i6, add2(i6, NEG2));
        float w = h ? 0.5f : 1.0f;
        a3 = fma2(term, pk2(w, w), a3);
    }
#undef UNIT

    u64 accp = add2(add2(a0, a1), add2(a2, a3));
    float al, ah;
    asm("mov.b64 {%0,%1}, %2;" : "=f"(al), "=f"(ah) : "l"(accp));
    float acc = al + ah;

    // Oscillator terms: only h=0 threads contribute (each particle once).
    float sx = 0.f, sy = 0.f, sz = 0.f, ssq = 0.f;
    if (h == 0) {
        float xlo, xhi, ylo, yhi, zlo, zhi;
        asm("mov.b64 {%0,%1}, %2;" : "=f"(xlo), "=f"(xhi) : "l"(qx));
        asm("mov.b64 {%0,%1}, %2;" : "=f"(ylo), "=f"(yhi) : "l"(qy));
        asm("mov.b64 {%0,%1}, %2;" : "=f"(zlo), "=f"(zhi) : "l"(qz));
        sx = xlo + xhi;
        sy = ylo + yhi;
        sz = zlo + zhi;
        ssq = fmaf(xlo, xlo, fmaf(ylo, ylo, zlo * zlo))
            + fmaf(xhi, xhi, fmaf(yhi, yhi, zhi * zhi));
    }

    // Block reduction of 5 values: acc(LJ), sum_x, sum_y, sum_z, sum_sq
    float v[5] = {acc, sx, sy, sz, ssq};
    const unsigned FULL = 0xFFFFFFFFu;
    #pragma unroll
    for (int q = 0; q < 5; ++q) {
        float r = v[q];
        r += __shfl_down_sync(FULL, r, 16);
        r += __shfl_down_sync(FULL, r, 8);
        r += __shfl_down_sync(FULL, r, 4);
        r += __shfl_down_sync(FULL, r, 2);
        r += __shfl_down_sync(FULL, r, 1);
        v[q] = r;
    }
    const int warp = t >> 5;
    const int lane = t & 31;
    if (lane == 0) {
        #pragma unroll
        for (int q = 0; q < 5; ++q) red[q][warp] = v[q];
    }
    __syncthreads();
    if (warp == 0) {
        float r[5];
        #pragma unroll
        for (int q = 0; q < 5; ++q) {
            float val = (lane < 16) ? red[q][lane] : 0.0f;
            val += __shfl_down_sync(FULL, val, 8);
            val += __shfl_down_sync(FULL, val, 4);
            val += __shfl_down_sync(FULL, val, 2);
            val += __shfl_down_sync(FULL, val, 1);
            r[q] = val;
        }
        if (lane == 0) {
            float lj_total = 2.0f * r[0];
            float mean_sq = (r[1] * r[1] + r[2] * r[2] + r[3] * r[3]) * (1.0f / NP);
            float osc = 0.5f * (r[4] - mean_sq);
            out[b] = lj_total + osc;
        }
    }
}

extern "C" void kernel_launch(void* const* d_in, const int* in_sizes, int n_in,
                              void* d_out, int out_size) {
    const float* x = (const float*)d_in[0];
    float* out = (float*)d_out;
    int batches = in_sizes[0] / (NP * 3);   // 128
    lj_osc_kernel<<<batches, NP>>>(x, out);
}